// round 1
// baseline (speedup 1.0000x reference)
#include <cuda_runtime.h>
#include <cstdint>
#include <math.h>

// Problem dims
#define BB 16
#define NN 64
#define DD 512
#define PP 64
#define QQ 16
#define CELL 1024   // PP*QQ

// Output offsets (flat concat of reference return tuple, fp32)
#define OFF_M     0LL
#define OFF_MP    67108864LL
#define OFF_Q     134217728LL
#define OFF_K     134742016LL
#define OFF_COS   135266304LL
#define OFF_ABN   135266320LL
#define OFF_ABDJ  135274512LL
#define OFF_CT    135798800LL
#define OFF_CS    135864336LL
#define OFF_CDBL  135929872LL
#define OFF_PHAT  135995408LL

// Scratch (__device__ globals: allocation-free)
__device__ float g_dbar[BB * QQ];                 // mean_j d_ctx[b,j,q]
__device__ float g_bias_bar[NN * CELL];           // mean_j bias_m[i,j,c]
__device__ float g_wqd[BB * DD * PP];             // sum_q dbar*w_q
__device__ float g_wkd[BB * DD * PP];
__device__ float g_bqp[16 * DD * NN];             // K-split partials of bias_bar @ w_q^T
__device__ float g_bkp[16 * DD * NN];
__device__ float g_bq[DD * NN];
__device__ float g_bk[DD * NN];

// ---------------------------------------------------------------------------
// K0: per-batch setup — cos_ab, abn (outputs), dbar (scratch)
// grid=16 (one per b), block=128
__global__ void k_setup(const float* __restrict__ a, const float* __restrict__ b_,
                        const float* __restrict__ dctx, float* __restrict__ out) {
    int b = blockIdx.x;
    int t = threadIdx.x;
    __shared__ float ra[128], rb[128], rab[128];
    __shared__ float s_cos;
    float sa = 0.f, sb = 0.f, sab = 0.f;
    for (int d = t; d < DD; d += 128) {
        float av = a[b * DD + d], bv = b_[b * DD + d];
        sa += av * av; sb += bv * bv; sab += av * bv;
    }
    ra[t] = sa; rb[t] = sb; rab[t] = sab;
    __syncthreads();
    for (int s = 64; s > 0; s >>= 1) {
        if (t < s) { ra[t] += ra[t + s]; rb[t] += rb[t + s]; rab[t] += rab[t + s]; }
        __syncthreads();
    }
    if (t == 0) {
        float na = fmaxf(sqrtf(ra[0]), 1e-8f);
        float nb = fmaxf(sqrtf(rb[0]), 1e-8f);
        float cosv = rab[0] / (na * nb);
        s_cos = cosv;
        out[OFF_COS + b] = cosv;
    }
    __syncthreads();
    float cosv = s_cos;
    for (int d = t; d < DD; d += 128) {
        out[OFF_ABN + (long long)b * DD + d] =
            tanhf(a[b * DD + d] * (1.f - cosv)) + tanhf(b_[b * DD + d] * cosv);
    }
    if (t < QQ) {
        float s = 0.f;
        for (int j = 0; j < NN; j++) s += dctx[(b * NN + j) * QQ + t];
        g_dbar[b * QQ + t] = s * (1.f / NN);
    }
}

// ---------------------------------------------------------------------------
// K1: bias_bar[i,c] = mean_j bias_m[i,j,c]   grid=256, block=256
__global__ void k_biasbar(const float* __restrict__ bias) {
    int idx = blockIdx.x * 256 + threadIdx.x;   // 65536 total
    int i = idx >> 10, c = idx & 1023;
    float s = 0.f;
    const float* base = bias + (size_t)i * NN * CELL + c;
#pragma unroll 8
    for (int j = 0; j < NN; j++) s += base[(size_t)j * CELL];
    g_bias_bar[idx] = s * (1.f / NN);
}

// ---------------------------------------------------------------------------
// K2: wqd[b,d,p] = sum_q dbar[b,q]*w_q[d,p*16+q] (and wkd)  grid=2048, block=256
__global__ void k_wd(const float* __restrict__ wq, const float* __restrict__ wk) {
    int gid = blockIdx.x * 256 + threadIdx.x;   // B*D*P = 524288
    int b = gid >> 15;
    int dp = gid & 32767;
    int d = dp >> 6, p = dp & 63;
    const float* wqr = wq + (size_t)d * CELL + p * QQ;
    const float* wkr = wk + (size_t)d * CELL + p * QQ;
    const float* db = g_dbar + b * QQ;
    float sq = 0.f, sk = 0.f;
#pragma unroll
    for (int q = 0; q < QQ; q++) {
        float dv = db[q];
        sq += dv * wqr[q];
        sk += dv * wkr[q];
    }
    g_wqd[gid] = sq;
    g_wkd[gid] = sk;
}

// ---------------------------------------------------------------------------
// K3: BQ/BK partials: tile GEMM 32d x 64n over K-chunk of 64.
// grid=(16 dtiles, 16 ksplits), block=(16,8)
__global__ void k_bqpart(const float* __restrict__ wq, const float* __restrict__ wk) {
    __shared__ float sb[64 * 65];    // bias_bar tile [n][k], padded
    __shared__ float swq[32 * 64];   // w_q tile [d][k]
    __shared__ float swk[32 * 64];
    int dt = blockIdx.x, ks = blockIdx.y;
    int tx = threadIdx.x, ty = threadIdx.y;
    int tid = ty * 16 + tx;          // 0..127
    int k0 = ks * 64;

    // load bias_bar tile: 64x64 floats = 1024 float4 / 128 thr = 8 each
    for (int it = 0; it < 8; it++) {
        int idx = tid + 128 * it;            // 0..1023
        int r = idx >> 4, cv = idx & 15;
        float4 v = *(const float4*)(g_bias_bar + r * CELL + k0 + cv * 4);
        sb[r * 65 + cv * 4 + 0] = v.x; sb[r * 65 + cv * 4 + 1] = v.y;
        sb[r * 65 + cv * 4 + 2] = v.z; sb[r * 65 + cv * 4 + 3] = v.w;
    }
    // load w tiles: 32x64 floats = 512 float4 / 128 thr = 4 each
    for (int it = 0; it < 4; it++) {
        int idx = tid + 128 * it;            // 0..511
        int r = idx >> 4, cv = idx & 15;
        float4 q = *(const float4*)(wq + (size_t)(dt * 32 + r) * CELL + k0 + cv * 4);
        float4 k = *(const float4*)(wk + (size_t)(dt * 32 + r) * CELL + k0 + cv * 4);
        swq[r * 64 + cv * 4 + 0] = q.x; swq[r * 64 + cv * 4 + 1] = q.y;
        swq[r * 64 + cv * 4 + 2] = q.z; swq[r * 64 + cv * 4 + 3] = q.w;
        swk[r * 64 + cv * 4 + 0] = k.x; swk[r * 64 + cv * 4 + 1] = k.y;
        swk[r * 64 + cv * 4 + 2] = k.z; swk[r * 64 + cv * 4 + 3] = k.w;
    }
    __syncthreads();

    float accq[4][4] = {}, acck[4][4] = {};
    for (int kk = 0; kk < 64; kk++) {
        float aq[4], ak[4], bv[4];
#pragma unroll
        for (int i = 0; i < 4; i++) {
            aq[i] = swq[(ty * 4 + i) * 64 + kk];
            ak[i] = swk[(ty * 4 + i) * 64 + kk];
        }
#pragma unroll
        for (int j = 0; j < 4; j++) bv[j] = sb[(tx * 4 + j) * 65 + kk];
#pragma unroll
        for (int i = 0; i < 4; i++)
#pragma unroll
            for (int j = 0; j < 4; j++) {
                accq[i][j] += aq[i] * bv[j];
                acck[i][j] += ak[i] * bv[j];
            }
    }
#pragma unroll
    for (int i = 0; i < 4; i++)
#pragma unroll
        for (int j = 0; j < 4; j++) {
            int d = dt * 32 + ty * 4 + i;
            int n = tx * 4 + j;
            g_bqp[ks * (DD * NN) + d * NN + n] = accq[i][j];
            g_bkp[ks * (DD * NN) + d * NN + n] = acck[i][j];
        }
}

// K3b: reduce the 16 K-split partials.  grid=128, block=256
__global__ void k_bqreduce() {
    int idx = blockIdx.x * 256 + threadIdx.x;  // 32768
    float sq = 0.f, sk = 0.f;
#pragma unroll
    for (int ks = 0; ks < 16; ks++) {
        sq += g_bqp[ks * (DD * NN) + idx];
        sk += g_bkp[ks * (DD * NN) + idx];
    }
    g_bq[idx] = sq;
    g_bk[idx] = sk;
}

// ---------------------------------------------------------------------------
// K4: q_proj/k_proj: s3 * (wqd[b] @ c[b]^T) + t * BQ   (P=64 inner dim)
// grid=(16 dtiles of 32, 16 b), block=(16,8)
__global__ void k_proj(const float* __restrict__ c, const float* __restrict__ alpha,
                       float* __restrict__ out) {
    __shared__ float sc[64 * 65];    // c[b] tile [n][p], padded
    __shared__ float swq[32 * 64];   // wqd[b] tile [d][p]
    __shared__ float swk[32 * 64];
    int dt = blockIdx.x, b = blockIdx.y;
    int tx = threadIdx.x, ty = threadIdx.y;
    int tid = ty * 16 + tx;
    float ap = 1.f + alpha[0];
    float s3 = ap * ap * ap;
    float tb = ap * ap + ap + 1.f;

    for (int it = 0; it < 8; it++) {
        int idx = tid + 128 * it;            // 0..1023
        int r = idx >> 4, cv = idx & 15;
        float4 v = *(const float4*)(c + (size_t)(b * NN + r) * PP + cv * 4);
        sc[r * 65 + cv * 4 + 0] = v.x; sc[r * 65 + cv * 4 + 1] = v.y;
        sc[r * 65 + cv * 4 + 2] = v.z; sc[r * 65 + cv * 4 + 3] = v.w;
    }
    for (int it = 0; it < 4; it++) {
        int idx = tid + 128 * it;            // 0..511
        int r = idx >> 4, cv = idx & 15;
        size_t src = (size_t)b * (DD * PP) + (size_t)(dt * 32 + r) * PP + cv * 4;
        float4 q = *(const float4*)(g_wqd + src);
        float4 k = *(const float4*)(g_wkd + src);
        swq[r * 64 + cv * 4 + 0] = q.x; swq[r * 64 + cv * 4 + 1] = q.y;
        swq[r * 64 + cv * 4 + 2] = q.z; swq[r * 64 + cv * 4 + 3] = q.w;
        swk[r * 64 + cv * 4 + 0] = k.x; swk[r * 64 + cv * 4 + 1] = k.y;
        swk[r * 64 + cv * 4 + 2] = k.z; swk[r * 64 + cv * 4 + 3] = k.w;
    }
    __syncthreads();

    float accq[4][4] = {}, acck[4][4] = {};
    for (int p = 0; p < PP; p++) {
        float aq[4], ak[4], bv[4];
#pragma unroll
        for (int i = 0; i < 4; i++) {
            aq[i] = swq[(ty * 4 + i) * 64 + p];
            ak[i] = swk[(ty * 4 + i) * 64 + p];
        }
#pragma unroll
        for (int j = 0; j < 4; j++) bv[j] = sc[(tx * 4 + j) * 65 + p];
#pragma unroll
        for (int i = 0; i < 4; i++)
#pragma unroll
            for (int j = 0; j < 4; j++) {
                accq[i][j] += aq[i] * bv[j];
                acck[i][j] += ak[i] * bv[j];
            }
    }
#pragma unroll
    for (int i = 0; i < 4; i++)
#pragma unroll
        for (int j = 0; j < 4; j++) {
            int d = dt * 32 + ty * 4 + i;
            int n = tx * 4 + j;
            long long o = (long long)b * (DD * NN) + d * NN + n;
            out[OFF_Q + o] = s3 * accq[i][j] + tb * g_bq[d * NN + n];
            out[OFF_K + o] = s3 * acck[i][j] + tb * g_bk[d * NN + n];
        }
}

// ---------------------------------------------------------------------------
// K5: tail — c_tilde, c_star, abdj, p_hat, c_dbl.  grid=B*N=1024, block=128
__global__ void k_tail(const float* __restrict__ c, const float* __restrict__ dctx,
                       const float* __restrict__ abd_w, const float* __restrict__ abd_b,
                       const float* __restrict__ ctx_w, const float* __restrict__ ctx_b,
                       const float* __restrict__ w1, const float* __restrict__ b1,
                       const float* __restrict__ w_prob, const float* __restrict__ b_prob,
                       float* __restrict__ out) {
    int bn = blockIdx.x;
    int b = bn >> 6, n = bn & 63;
    int t = threadIdx.x;
    __shared__ float s_ct[64], s_cs[64], s_abdj[512], s_d[16];
    __shared__ float red[128], red2[128];
    __shared__ float s_stat[2], s_p[2];

    if (t < QQ) s_d[t] = dctx[bn * QQ + t];
    float v = 0.f;
    if (t < 64) { v = 64.f * c[(size_t)bn * 64 + t]; s_ct[t] = v; }
    __syncthreads();
    if (t < 32) {
        float m = fmaxf(s_ct[t], s_ct[t + 32]);
#pragma unroll
        for (int o = 16; o > 0; o >>= 1) m = fmaxf(m, __shfl_xor_sync(0xffffffffu, m, o));
        if (t == 0) s_stat[0] = m;
    }
    __syncthreads();
    float e = 0.f;
    if (t < 64) e = expf(v - s_stat[0]);
    red[t] = (t < 64) ? e : 0.f;
    __syncthreads();
    if (t < 32) {
        float s = red[t] + red[t + 32];
#pragma unroll
        for (int o = 16; o > 0; o >>= 1) s += __shfl_xor_sync(0xffffffffu, s, o);
        if (t == 0) s_stat[1] = s;
    }
    __syncthreads();
    if (t < 64) {
        float ct = e / s_stat[1];
        s_ct[t] = ct;
        out[OFF_CT + (long long)bn * 64 + t] = ct;
    }
    __syncthreads();

    // c_star
    if (t < 64) {
        float acc = b1[n * 64 + t];
        const float* w1r = w1 + ((size_t)n * 64 + t) * 64;
#pragma unroll 8
        for (int p = 0; p < 64; p++) acc += s_ct[p] * w1r[p];
        float cs = fmaxf(acc, 0.f);
        s_cs[t] = cs;
        out[OFF_CS + (long long)bn * 64 + t] = cs;
    }
    // abdj
    for (int d = t; d < DD; d += 128) {
        float dp = ctx_b[d];
        const float* cw = ctx_w + d * QQ;
#pragma unroll
        for (int q = 0; q < QQ; q++) dp += s_d[q] * cw[q];
        float abn = out[OFF_ABN + (long long)b * DD + d];
        float val = tanhf(abd_w[n * DD + d] * abn * dp + abd_b[n * DD + d]);
        s_abdj[d] = val;
        out[OFF_ABDJ + (long long)bn * DD + d] = val;
    }
    __syncthreads();

    // logits over combined = [c_star(64), abdj(512)]
    float l0 = 0.f, l1 = 0.f;
    const float* wp0 = w_prob + (size_t)(n * 2 + 0) * 576;
    const float* wp1 = w_prob + (size_t)(n * 2 + 1) * 576;
    for (int k = t; k < 576; k += 128) {
        float cb = (k < 64) ? s_cs[k] : s_abdj[k - 64];
        l0 += cb * wp0[k];
        l1 += cb * wp1[k];
    }
    red[t] = l0; red2[t] = l1;
    __syncthreads();
    for (int s = 64; s > 0; s >>= 1) {
        if (t < s) { red[t] += red[t + s]; red2[t] += red2[t + s]; }
        __syncthreads();
    }
    if (t == 0) {
        float L0 = red[0] + b_prob[n * 2 + 0];
        float L1 = red2[0] + b_prob[n * 2 + 1];
        float m = fmaxf(L0, L1);
        float e0 = expf(L0 - m), e1 = expf(L1 - m);
        float inv = 1.f / (e0 + e1);
        s_p[0] = e0 * inv; s_p[1] = e1 * inv;
        out[OFF_PHAT + (long long)bn * 2 + 0] = s_p[0];
        out[OFF_PHAT + (long long)bn * 2 + 1] = s_p[1];
    }
    __syncthreads();
    if (t < 64) {
        float cs = s_cs[t];
        out[OFF_CDBL + (long long)bn * 64 + t] = tanhf(s_p[0] * cs) + tanhf(s_p[1] * cs);
    }
}

// ---------------------------------------------------------------------------
// K6: the big HBM-bound kernel — m and m_p.
// grid = B*N = 1024 blocks (one per (b,i)), block=256, loop over j.
__global__ void k_big(const float* __restrict__ c, const float* __restrict__ dctx,
                      const float* __restrict__ bias, const float* __restrict__ alpha,
                      float* __restrict__ out) {
    int b = blockIdx.x >> 6;
    int i = blockIdx.x & 63;
    int t = threadIdx.x;
    float ap = 1.f + alpha[0];
    float s3 = ap * ap * ap;
    float tb = ap * ap + ap + 1.f;

    __shared__ float4 ds[256];  // d_ctx[b] : 64 rows x 16 floats = 256 float4
    ds[t] = ((const float4*)(dctx + (size_t)b * NN * QQ))[t];

    int p = t >> 2;
    int qv = t & 3;
    float cv = c[((size_t)b * NN + i) * PP + p];
    __syncthreads();

    const float4* bias4 = (const float4*)bias + (size_t)i * (NN * CELL / 4);
    float4* m4 = (float4*)out + ((size_t)b * NN + i) * (NN * CELL / 4);
    float4* mp4 = m4 + (OFF_MP / 4);

#pragma unroll 4
    for (int j = 0; j < NN; j++) {
        float4 d4 = ds[j * 4 + qv];
        float4 mv;
        mv.x = cv * d4.x; mv.y = cv * d4.y; mv.z = cv * d4.z; mv.w = cv * d4.w;
        float4 bv = bias4[j * 256 + t];
        float4 mp;
        mp.x = s3 * mv.x + tb * bv.x;
        mp.y = s3 * mv.y + tb * bv.y;
        mp.z = s3 * mv.z + tb * bv.z;
        mp.w = s3 * mv.w + tb * bv.w;
        __stcs(&m4[j * 256 + t], mv);
        __stcs(&mp4[j * 256 + t], mp);
    }
}

// ---------------------------------------------------------------------------
extern "C" void kernel_launch(void* const* d_in, const int* in_sizes, int n_in,
                              void* d_out, int out_size) {
    const float* a      = (const float*)d_in[0];
    const float* b      = (const float*)d_in[1];
    const float* c      = (const float*)d_in[2];
    const float* dctx   = (const float*)d_in[3];
    const float* alpha  = (const float*)d_in[4];
    const float* bias   = (const float*)d_in[5];
    const float* wq     = (const float*)d_in[6];
    const float* wk     = (const float*)d_in[7];
    const float* abd_w  = (const float*)d_in[8];
    const float* abd_b  = (const float*)d_in[9];
    const float* ctx_w  = (const float*)d_in[10];
    const float* ctx_b  = (const float*)d_in[11];
    const float* w1     = (const float*)d_in[12];
    const float* b1     = (const float*)d_in[13];
    const float* w_prob = (const float*)d_in[14];
    const float* b_prob = (const float*)d_in[15];
    float* out = (float*)d_out;

    k_setup<<<BB, 128>>>(a, b, dctx, out);
    k_biasbar<<<256, 256>>>(bias);
    k_wd<<<2048, 256>>>(wq, wk);
    k_bqpart<<<dim3(16, 16), dim3(16, 8)>>>(wq, wk);
    k_bqreduce<<<128, 256>>>();
    k_proj<<<dim3(16, 16), dim3(16, 8)>>>(c, alpha, out);
    k_tail<<<BB * NN, 128>>>(c, dctx, abd_w, abd_b, ctx_w, ctx_b,
                             w1, b1, w_prob, b_prob, out);
    k_big<<<BB * NN, 256>>>(c, dctx, bias, alpha, out);
}

// round 2
// speedup vs baseline: 1.0645x; 1.0645x over previous
#include <cuda_runtime.h>
#include <cstdint>
#include <math.h>

// Problem dims
#define BB 16
#define NN 64
#define DD 512
#define PP 64
#define QQ 16
#define CELL 1024   // PP*QQ

// Output offsets (flat concat of reference return tuple, fp32)
#define OFF_M     0LL
#define OFF_MP    67108864LL
#define OFF_Q     134217728LL
#define OFF_K     134742016LL
#define OFF_COS   135266304LL
#define OFF_ABN   135266320LL
#define OFF_ABDJ  135274512LL
#define OFF_CT    135798800LL
#define OFF_CS    135864336LL
#define OFF_CDBL  135929872LL
#define OFF_PHAT  135995408LL

// Scratch (__device__ globals: allocation-free)
__device__ float g_bias_bar[NN * CELL];           // mean_j bias_m[i,j,c]
__device__ float g_wqd[BB * DD * PP];             // sum_q dbar*w_q
__device__ float g_wkd[BB * DD * PP];
__device__ float g_bqp[32 * DD * NN];             // K-split partials of bias_bar @ w_q^T
__device__ float g_bkp[32 * DD * NN];
__device__ float g_bq[DD * NN];
__device__ float g_bk[DD * NN];

// ---------------------------------------------------------------------------
// K_pre: fused independent preprocessing. grid = 16 + 256 + 2048, block=256
//   blocks [0,16):    per-batch cos_ab, abn
//   blocks [16,272):  bias_bar[i,c] = mean_j bias_m[i,j,c]
//   blocks [272,2320): wqd/wkd (self-computes dbar per block)
__global__ void k_pre(const float* __restrict__ a, const float* __restrict__ b_,
                      const float* __restrict__ dctx, const float* __restrict__ bias,
                      const float* __restrict__ wq, const float* __restrict__ wk,
                      float* __restrict__ out) {
    int blk = blockIdx.x;
    int t = threadIdx.x;

    if (blk < 16) {
        int b = blk;
        __shared__ float ra[256], rb[256], rab[256];
        __shared__ float s_cos;
        float sa = 0.f, sb = 0.f, sab = 0.f;
        for (int d = t; d < DD; d += 256) {
            float av = a[b * DD + d], bv = b_[b * DD + d];
            sa += av * av; sb += bv * bv; sab += av * bv;
        }
        ra[t] = sa; rb[t] = sb; rab[t] = sab;
        __syncthreads();
        for (int s = 128; s > 0; s >>= 1) {
            if (t < s) { ra[t] += ra[t + s]; rb[t] += rb[t + s]; rab[t] += rab[t + s]; }
            __syncthreads();
        }
        if (t == 0) {
            float na = fmaxf(sqrtf(ra[0]), 1e-8f);
            float nb = fmaxf(sqrtf(rb[0]), 1e-8f);
            float cosv = rab[0] / (na * nb);
            s_cos = cosv;
            out[OFF_COS + b] = cosv;
        }
        __syncthreads();
        float cosv = s_cos;
        for (int d = t; d < DD; d += 256) {
            out[OFF_ABN + (long long)b * DD + d] =
                tanhf(a[b * DD + d] * (1.f - cosv)) + tanhf(b_[b * DD + d] * cosv);
        }
    } else if (blk < 272) {
        int idx = (blk - 16) * 256 + t;        // 65536 total
        int i = idx >> 10, c = idx & 1023;
        float s = 0.f;
        const float* base = bias + (size_t)i * NN * CELL + c;
#pragma unroll 8
        for (int j = 0; j < NN; j++) s += base[(size_t)j * CELL];
        g_bias_bar[idx] = s * (1.f / NN);
    } else {
        int blk2 = blk - 272;                  // 0..2047
        int gid0 = blk2 * 256;
        int b = gid0 >> 15;                    // constant per block
        __shared__ float s_part[256];
        __shared__ float s_dbar[16];
        // compute dbar[b,:] redundantly per block (cheap)
        {
            int q = t & 15, g = t >> 4;
            const float* dbase = dctx + (size_t)b * NN * QQ;
            float s = 0.f;
#pragma unroll
            for (int jj = 0; jj < 4; jj++) s += dbase[(g * 4 + jj) * QQ + q];
            s_part[t] = s;
            __syncthreads();
            if (t < 16) {
                float acc = 0.f;
#pragma unroll
                for (int gg = 0; gg < 16; gg++) acc += s_part[gg * 16 + t];
                s_dbar[t] = acc * (1.f / NN);
            }
            __syncthreads();
        }
        int gid = gid0 + t;
        int dp = gid & 32767;
        int d = dp >> 6, p = dp & 63;
        const float* wqr = wq + (size_t)d * CELL + p * QQ;
        const float* wkr = wk + (size_t)d * CELL + p * QQ;
        float sq = 0.f, sk = 0.f;
#pragma unroll
        for (int q = 0; q < QQ; q++) {
            float dv = s_dbar[q];
            sq += dv * wqr[q];
            sk += dv * wkr[q];
        }
        g_wqd[gid] = sq;
        g_wkd[gid] = sk;
    }
}

// ---------------------------------------------------------------------------
// K_bq: BQ/BK partials, K-split 32 (K=32 each). grid=(16 dt, 32 ks), block=(16,8)
__global__ void k_bqpart(const float* __restrict__ wq, const float* __restrict__ wk) {
    __shared__ float sb[64 * 33];
    __shared__ float swq[32 * 33];
    __shared__ float swk[32 * 33];
    int dt = blockIdx.x, ks = blockIdx.y;
    int tx = threadIdx.x, ty = threadIdx.y;
    int tid = ty * 16 + tx;          // 0..127
    int k0 = ks * 32;

    // bias_bar tile 64x32 = 512 float4 / 128 thr = 4 iters (8 f4 per row)
#pragma unroll
    for (int it = 0; it < 4; it++) {
        int idx = tid + 128 * it;
        int r = idx >> 3, cv = idx & 7;
        float4 v = *(const float4*)(g_bias_bar + r * CELL + k0 + cv * 4);
        sb[r * 33 + cv * 4 + 0] = v.x; sb[r * 33 + cv * 4 + 1] = v.y;
        sb[r * 33 + cv * 4 + 2] = v.z; sb[r * 33 + cv * 4 + 3] = v.w;
    }
    // w tiles 32x32 = 256 float4 -> 2 iters each
#pragma unroll
    for (int it = 0; it < 2; it++) {
        int idx = tid + 128 * it;
        int r = idx >> 3, cv = idx & 7;
        float4 q = *(const float4*)(wq + (size_t)(dt * 32 + r) * CELL + k0 + cv * 4);
        float4 k = *(const float4*)(wk + (size_t)(dt * 32 + r) * CELL + k0 + cv * 4);
        swq[r * 33 + cv * 4 + 0] = q.x; swq[r * 33 + cv * 4 + 1] = q.y;
        swq[r * 33 + cv * 4 + 2] = q.z; swq[r * 33 + cv * 4 + 3] = q.w;
        swk[r * 33 + cv * 4 + 0] = k.x; swk[r * 33 + cv * 4 + 1] = k.y;
        swk[r * 33 + cv * 4 + 2] = k.z; swk[r * 33 + cv * 4 + 3] = k.w;
    }
    __syncthreads();

    float accq[4][4] = {}, acck[4][4] = {};
    for (int kk = 0; kk < 32; kk++) {
        float aq[4], ak[4], bv[4];
#pragma unroll
        for (int i = 0; i < 4; i++) {
            aq[i] = swq[(ty * 4 + i) * 33 + kk];
            ak[i] = swk[(ty * 4 + i) * 33 + kk];
        }
#pragma unroll
        for (int j = 0; j < 4; j++) bv[j] = sb[(tx * 4 + j) * 33 + kk];
#pragma unroll
        for (int i = 0; i < 4; i++)
#pragma unroll
            for (int j = 0; j < 4; j++) {
                accq[i][j] += aq[i] * bv[j];
                acck[i][j] += ak[i] * bv[j];
            }
    }
#pragma unroll
    for (int i = 0; i < 4; i++)
#pragma unroll
        for (int j = 0; j < 4; j++) {
            int d = dt * 32 + ty * 4 + i;
            int n = tx * 4 + j;
            g_bqp[ks * (DD * NN) + d * NN + n] = accq[i][j];
            g_bkp[ks * (DD * NN) + d * NN + n] = acck[i][j];
        }
}

// ---------------------------------------------------------------------------
// K_tail: tail math (blocks <1024) + BQ/BK partial reduction (blocks 1024..1151)
// grid = 1152, block = 128
__global__ void k_tail(const float* __restrict__ c, const float* __restrict__ dctx,
                       const float* __restrict__ abd_w, const float* __restrict__ abd_b,
                       const float* __restrict__ ctx_w, const float* __restrict__ ctx_b,
                       const float* __restrict__ w1, const float* __restrict__ b1,
                       const float* __restrict__ w_prob, const float* __restrict__ b_prob,
                       float* __restrict__ out) {
    int bn = blockIdx.x;
    int t = threadIdx.x;

    if (bn >= 1024) {
        int rb = bn - 1024;                     // 0..127
#pragma unroll
        for (int it = 0; it < 2; it++) {
            int idx = rb * 256 + it * 128 + t;  // 32768 total
            float sq = 0.f, sk = 0.f;
#pragma unroll
            for (int ks = 0; ks < 32; ks++) {
                sq += g_bqp[ks * (DD * NN) + idx];
                sk += g_bkp[ks * (DD * NN) + idx];
            }
            g_bq[idx] = sq;
            g_bk[idx] = sk;
        }
        return;
    }

    int b = bn >> 6, n = bn & 63;
    __shared__ float s_ct[64], s_cs[64], s_abdj[512], s_d[16];
    __shared__ float red[128], red2[128];
    __shared__ float s_stat[2], s_p[2];

    if (t < QQ) s_d[t] = dctx[bn * QQ + t];
    float v = 0.f;
    if (t < 64) { v = 64.f * c[(size_t)bn * 64 + t]; s_ct[t] = v; }
    __syncthreads();
    if (t < 32) {
        float m = fmaxf(s_ct[t], s_ct[t + 32]);
#pragma unroll
        for (int o = 16; o > 0; o >>= 1) m = fmaxf(m, __shfl_xor_sync(0xffffffffu, m, o));
        if (t == 0) s_stat[0] = m;
    }
    __syncthreads();
    float e = 0.f;
    if (t < 64) e = expf(v - s_stat[0]);
    red[t] = (t < 64) ? e : 0.f;
    __syncthreads();
    if (t < 32) {
        float s = red[t] + red[t + 32];
#pragma unroll
        for (int o = 16; o > 0; o >>= 1) s += __shfl_xor_sync(0xffffffffu, s, o);
        if (t == 0) s_stat[1] = s;
    }
    __syncthreads();
    if (t < 64) {
        float ct = e / s_stat[1];
        s_ct[t] = ct;
        out[OFF_CT + (long long)bn * 64 + t] = ct;
    }
    __syncthreads();

    // c_star
    if (t < 64) {
        float acc = b1[n * 64 + t];
        const float* w1r = w1 + ((size_t)n * 64 + t) * 64;
#pragma unroll 8
        for (int p = 0; p < 64; p++) acc += s_ct[p] * w1r[p];
        float cs = fmaxf(acc, 0.f);
        s_cs[t] = cs;
        out[OFF_CS + (long long)bn * 64 + t] = cs;
    }
    // abdj
    for (int d = t; d < DD; d += 128) {
        float dp = ctx_b[d];
        const float* cw = ctx_w + d * QQ;
#pragma unroll
        for (int q = 0; q < QQ; q++) dp += s_d[q] * cw[q];
        float abn = out[OFF_ABN + (long long)b * DD + d];
        float val = tanhf(abd_w[n * DD + d] * abn * dp + abd_b[n * DD + d]);
        s_abdj[d] = val;
        out[OFF_ABDJ + (long long)bn * DD + d] = val;
    }
    __syncthreads();

    // logits over combined = [c_star(64), abdj(512)]
    float l0 = 0.f, l1 = 0.f;
    const float* wp0 = w_prob + (size_t)(n * 2 + 0) * 576;
    const float* wp1 = w_prob + (size_t)(n * 2 + 1) * 576;
    for (int k = t; k < 576; k += 128) {
        float cb = (k < 64) ? s_cs[k] : s_abdj[k - 64];
        l0 += cb * wp0[k];
        l1 += cb * wp1[k];
    }
    red[t] = l0; red2[t] = l1;
    __syncthreads();
    for (int s = 64; s > 0; s >>= 1) {
        if (t < s) { red[t] += red[t + s]; red2[t] += red2[t + s]; }
        __syncthreads();
    }
    if (t == 0) {
        float L0 = red[0] + b_prob[n * 2 + 0];
        float L1 = red2[0] + b_prob[n * 2 + 1];
        float m = fmaxf(L0, L1);
        float e0 = expf(L0 - m), e1 = expf(L1 - m);
        float inv = 1.f / (e0 + e1);
        s_p[0] = e0 * inv; s_p[1] = e1 * inv;
        out[OFF_PHAT + (long long)bn * 2 + 0] = s_p[0];
        out[OFF_PHAT + (long long)bn * 2 + 1] = s_p[1];
    }
    __syncthreads();
    if (t < 64) {
        float cs = s_cs[t];
        out[OFF_CDBL + (long long)bn * 64 + t] = tanhf(s_p[0] * cs) + tanhf(s_p[1] * cs);
    }
}

// ---------------------------------------------------------------------------
// K_proj: q_proj/k_proj = s3*(wqd[b] @ c[b]^T) + tb*BQ.  256 threads, 2x4 tiles.
// grid=(16 dtiles of 32, 16 b), block=(16,16)
__global__ void k_proj(const float* __restrict__ c, const float* __restrict__ alpha,
                       float* __restrict__ out) {
    __shared__ float sc[64 * 65];    // c[b] tile [n][p], padded
    __shared__ float swq[32 * 65];   // wqd[b] tile [d][p], padded
    __shared__ float swk[32 * 65];
    int dt = blockIdx.x, b = blockIdx.y;
    int tx = threadIdx.x, ty = threadIdx.y;
    int tid = ty * 16 + tx;          // 0..255
    float ap = 1.f + alpha[0];
    float s3 = ap * ap * ap;
    float tb = ap * ap + ap + 1.f;

    // c tile: 64x64 = 1024 float4 / 256 thr = 4 iters
#pragma unroll
    for (int it = 0; it < 4; it++) {
        int idx = tid + 256 * it;
        int r = idx >> 4, cv = idx & 15;
        float4 v = *(const float4*)(c + (size_t)(b * NN + r) * PP + cv * 4);
        sc[r * 65 + cv * 4 + 0] = v.x; sc[r * 65 + cv * 4 + 1] = v.y;
        sc[r * 65 + cv * 4 + 2] = v.z; sc[r * 65 + cv * 4 + 3] = v.w;
    }
    // wqd/wkd tiles: 32x64 = 512 float4 / 256 = 2 iters
#pragma unroll
    for (int it = 0; it < 2; it++) {
        int idx = tid + 256 * it;
        int r = idx >> 4, cv = idx & 15;
        size_t src = (size_t)b * (DD * PP) + (size_t)(dt * 32 + r) * PP + cv * 4;
        float4 q = *(const float4*)(g_wqd + src);
        float4 k = *(const float4*)(g_wkd + src);
        swq[r * 65 + cv * 4 + 0] = q.x; swq[r * 65 + cv * 4 + 1] = q.y;
        swq[r * 65 + cv * 4 + 2] = q.z; swq[r * 65 + cv * 4 + 3] = q.w;
        swk[r * 65 + cv * 4 + 0] = k.x; swk[r * 65 + cv * 4 + 1] = k.y;
        swk[r * 65 + cv * 4 + 2] = k.z; swk[r * 65 + cv * 4 + 3] = k.w;
    }
    __syncthreads();

    float accq[2][4] = {}, acck[2][4] = {};
    for (int p = 0; p < PP; p++) {
        float aq[2], ak[2], bv[4];
#pragma unroll
        for (int i = 0; i < 2; i++) {
            aq[i] = swq[(ty * 2 + i) * 65 + p];
            ak[i] = swk[(ty * 2 + i) * 65 + p];
        }
#pragma unroll
        for (int j = 0; j < 4; j++) bv[j] = sc[(tx * 4 + j) * 65 + p];
#pragma unroll
        for (int i = 0; i < 2; i++)
#pragma unroll
            for (int j = 0; j < 4; j++) {
                accq[i][j] += aq[i] * bv[j];
                acck[i][j] += ak[i] * bv[j];
            }
    }
#pragma unroll
    for (int i = 0; i < 2; i++)
#pragma unroll
        for (int j = 0; j < 4; j++) {
            int d = dt * 32 + ty * 2 + i;
            int n = tx * 4 + j;
            long long o = (long long)b * (DD * NN) + d * NN + n;
            out[OFF_Q + o] = s3 * accq[i][j] + tb * g_bq[d * NN + n];
            out[OFF_K + o] = s3 * acck[i][j] + tb * g_bk[d * NN + n];
        }
}

// ---------------------------------------------------------------------------
// K_big: the HBM-bound kernel — m and m_p (537 MB of stores).
// grid = B*N = 1024 blocks (one per (b,i)), block=256, loop over j.
__global__ void k_big(const float* __restrict__ c, const float* __restrict__ dctx,
                      const float* __restrict__ bias, const float* __restrict__ alpha,
                      float* __restrict__ out) {
    int b = blockIdx.x >> 6;
    int i = blockIdx.x & 63;
    int t = threadIdx.x;
    float ap = 1.f + alpha[0];
    float s3 = ap * ap * ap;
    float tb = ap * ap + ap + 1.f;

    __shared__ float4 ds[256];  // d_ctx[b] : 64 rows x 16 floats = 256 float4
    ds[t] = ((const float4*)(dctx + (size_t)b * NN * QQ))[t];

    int p = t >> 2;
    int qv = t & 3;
    float cv = c[((size_t)b * NN + i) * PP + p];
    __syncthreads();

    const float4* bias4 = (const float4*)bias + (size_t)i * (NN * CELL / 4);
    float4* m4 = (float4*)out + ((size_t)b * NN + i) * (NN * CELL / 4);
    float4* mp4 = m4 + (OFF_MP / 4);

#pragma unroll 4
    for (int j = 0; j < NN; j++) {
        float4 d4 = ds[j * 4 + qv];
        float4 mv;
        mv.x = cv * d4.x; mv.y = cv * d4.y; mv.z = cv * d4.z; mv.w = cv * d4.w;
        float4 bv = bias4[j * 256 + t];
        float4 mp;
        mp.x = s3 * mv.x + tb * bv.x;
        mp.y = s3 * mv.y + tb * bv.y;
        mp.z = s3 * mv.z + tb * bv.z;
        mp.w = s3 * mv.w + tb * bv.w;
        __stcs(&m4[j * 256 + t], mv);
        __stcs(&mp4[j * 256 + t], mp);
    }
}

// ---------------------------------------------------------------------------
extern "C" void kernel_launch(void* const* d_in, const int* in_sizes, int n_in,
                              void* d_out, int out_size) {
    const float* a      = (const float*)d_in[0];
    const float* b      = (const float*)d_in[1];
    const float* c      = (const float*)d_in[2];
    const float* dctx   = (const float*)d_in[3];
    const float* alpha  = (const float*)d_in[4];
    const float* bias   = (const float*)d_in[5];
    const float* wq     = (const float*)d_in[6];
    const float* wk     = (const float*)d_in[7];
    const float* abd_w  = (const float*)d_in[8];
    const float* abd_b  = (const float*)d_in[9];
    const float* ctx_w  = (const float*)d_in[10];
    const float* ctx_b  = (const float*)d_in[11];
    const float* w1     = (const float*)d_in[12];
    const float* b1     = (const float*)d_in[13];
    const float* w_prob = (const float*)d_in[14];
    const float* b_prob = (const float*)d_in[15];
    float* out = (float*)d_out;

    k_pre<<<2320, 256>>>(a, b, dctx, bias, wq, wk, out);
    k_bqpart<<<dim3(16, 32), dim3(16, 8)>>>(wq, wk);
    k_tail<<<1152, 128>>>(c, dctx, abd_w, abd_b, ctx_w, ctx_b,
                          w1, b1, w_prob, b_prob, out);
    k_proj<<<dim3(16, 16), dim3(16, 16)>>>(c, alpha, out);
    k_big<<<BB * NN, 256>>>(c, dctx, bias, alpha, out);
}

// round 3
// speedup vs baseline: 1.1907x; 1.1186x over previous
#include <cuda_runtime.h>
#include <cstdint>
#include <math.h>

// Problem dims
#define BB 16
#define NN 64
#define DD 512
#define PP 64
#define QQ 16
#define CELL 1024   // PP*QQ

// Output offsets (flat concat of reference return tuple, fp32)
#define OFF_M     0LL
#define OFF_MP    67108864LL
#define OFF_Q     134217728LL
#define OFF_K     134742016LL
#define OFF_COS   135266304LL
#define OFF_ABN   135266320LL
#define OFF_ABDJ  135274512LL
#define OFF_CT    135798800LL
#define OFF_CS    135864336LL
#define OFF_CDBL  135929872LL
#define OFF_PHAT  135995408LL

// Scratch (__device__ globals: allocation-free)
__device__ float g_bias_bar[NN * CELL];           // mean_j bias_m[i,j,c]
__device__ float g_wqd[BB * DD * PP];             // sum_q dbar*w_q
__device__ float g_wkd[BB * DD * PP];
__device__ float g_bqp[32 * DD * NN];             // K-split partials of bias_bar @ w_q^T
__device__ float g_bkp[32 * DD * NN];
__device__ float g_bq[DD * NN];
__device__ float g_bk[DD * NN];

// ---------------------------------------------------------------------------
// K_pre: fused independent preprocessing. grid = 16 + 256 + 2048, block=256
__global__ void k_pre(const float* __restrict__ a, const float* __restrict__ b_,
                      const float* __restrict__ dctx, const float* __restrict__ bias,
                      const float* __restrict__ wq, const float* __restrict__ wk,
                      float* __restrict__ out) {
    int blk = blockIdx.x;
    int t = threadIdx.x;

    if (blk < 16) {
        int b = blk;
        __shared__ float ra[256], rb[256], rab[256];
        __shared__ float s_cos;
        float sa = 0.f, sb = 0.f, sab = 0.f;
        for (int d = t; d < DD; d += 256) {
            float av = a[b * DD + d], bv = b_[b * DD + d];
            sa += av * av; sb += bv * bv; sab += av * bv;
        }
        ra[t] = sa; rb[t] = sb; rab[t] = sab;
        __syncthreads();
        for (int s = 128; s > 0; s >>= 1) {
            if (t < s) { ra[t] += ra[t + s]; rb[t] += rb[t + s]; rab[t] += rab[t + s]; }
            __syncthreads();
        }
        if (t == 0) {
            float na = fmaxf(sqrtf(ra[0]), 1e-8f);
            float nb = fmaxf(sqrtf(rb[0]), 1e-8f);
            float cosv = rab[0] / (na * nb);
            s_cos = cosv;
            out[OFF_COS + b] = cosv;
        }
        __syncthreads();
        float cosv = s_cos;
        for (int d = t; d < DD; d += 256) {
            out[OFF_ABN + (long long)b * DD + d] =
                tanhf(a[b * DD + d] * (1.f - cosv)) + tanhf(b_[b * DD + d] * cosv);
        }
    } else if (blk < 272) {
        int idx = (blk - 16) * 256 + t;        // 65536 total
        int i = idx >> 10, c = idx & 1023;
        float s = 0.f;
        const float* base = bias + (size_t)i * NN * CELL + c;
#pragma unroll 8
        for (int j = 0; j < NN; j++) s += base[(size_t)j * CELL];
        g_bias_bar[idx] = s * (1.f / NN);
    } else {
        int blk2 = blk - 272;                  // 0..2047
        int gid0 = blk2 * 256;
        int b = gid0 >> 15;                    // constant per block
        __shared__ float s_part[256];
        __shared__ float s_dbar[16];
        {
            int q = t & 15, g = t >> 4;
            const float* dbase = dctx + (size_t)b * NN * QQ;
            float s = 0.f;
#pragma unroll
            for (int jj = 0; jj < 4; jj++) s += dbase[(g * 4 + jj) * QQ + q];
            s_part[t] = s;
            __syncthreads();
            if (t < 16) {
                float acc = 0.f;
#pragma unroll
                for (int gg = 0; gg < 16; gg++) acc += s_part[gg * 16 + t];
                s_dbar[t] = acc * (1.f / NN);
            }
            __syncthreads();
        }
        int gid = gid0 + t;
        int dp = gid & 32767;
        int d = dp >> 6, p = dp & 63;
        const float* wqr = wq + (size_t)d * CELL + p * QQ;
        const float* wkr = wk + (size_t)d * CELL + p * QQ;
        float sq = 0.f, sk = 0.f;
#pragma unroll
        for (int q = 0; q < QQ; q++) {
            float dv = s_dbar[q];
            sq += dv * wqr[q];
            sk += dv * wkr[q];
        }
        g_wqd[gid] = sq;
        g_wkd[gid] = sk;
    }
}

// ---------------------------------------------------------------------------
// K_bq: BQ/BK partials, K-split 32 (K=32 each). grid=(16 dt, 32 ks), block=(16,8)
__global__ void k_bqpart(const float* __restrict__ wq, const float* __restrict__ wk) {
    __shared__ float sb[64 * 33];
    __shared__ float swq[32 * 33];
    __shared__ float swk[32 * 33];
    int dt = blockIdx.x, ks = blockIdx.y;
    int tx = threadIdx.x, ty = threadIdx.y;
    int tid = ty * 16 + tx;          // 0..127
    int k0 = ks * 32;

#pragma unroll
    for (int it = 0; it < 4; it++) {
        int idx = tid + 128 * it;
        int r = idx >> 3, cv = idx & 7;
        float4 v = *(const float4*)(g_bias_bar + r * CELL + k0 + cv * 4);
        sb[r * 33 + cv * 4 + 0] = v.x; sb[r * 33 + cv * 4 + 1] = v.y;
        sb[r * 33 + cv * 4 + 2] = v.z; sb[r * 33 + cv * 4 + 3] = v.w;
    }
#pragma unroll
    for (int it = 0; it < 2; it++) {
        int idx = tid + 128 * it;
        int r = idx >> 3, cv = idx & 7;
        float4 q = *(const float4*)(wq + (size_t)(dt * 32 + r) * CELL + k0 + cv * 4);
        float4 k = *(const float4*)(wk + (size_t)(dt * 32 + r) * CELL + k0 + cv * 4);
        swq[r * 33 + cv * 4 + 0] = q.x; swq[r * 33 + cv * 4 + 1] = q.y;
        swq[r * 33 + cv * 4 + 2] = q.z; swq[r * 33 + cv * 4 + 3] = q.w;
        swk[r * 33 + cv * 4 + 0] = k.x; swk[r * 33 + cv * 4 + 1] = k.y;
        swk[r * 33 + cv * 4 + 2] = k.z; swk[r * 33 + cv * 4 + 3] = k.w;
    }
    __syncthreads();

    float accq[4][4] = {}, acck[4][4] = {};
    for (int kk = 0; kk < 32; kk++) {
        float aq[4], ak[4], bv[4];
#pragma unroll
        for (int i = 0; i < 4; i++) {
            aq[i] = swq[(ty * 4 + i) * 33 + kk];
            ak[i] = swk[(ty * 4 + i) * 33 + kk];
        }
#pragma unroll
        for (int j = 0; j < 4; j++) bv[j] = sb[(tx * 4 + j) * 33 + kk];
#pragma unroll
        for (int i = 0; i < 4; i++)
#pragma unroll
            for (int j = 0; j < 4; j++) {
                accq[i][j] += aq[i] * bv[j];
                acck[i][j] += ak[i] * bv[j];
            }
    }
#pragma unroll
    for (int i = 0; i < 4; i++)
#pragma unroll
        for (int j = 0; j < 4; j++) {
            int d = dt * 32 + ty * 4 + i;
            int n = tx * 4 + j;
            g_bqp[ks * (DD * NN) + d * NN + n] = accq[i][j];
            g_bkp[ks * (DD * NN) + d * NN + n] = acck[i][j];
        }
}

// ---------------------------------------------------------------------------
// K_tail: tail math (blocks <1024) + BQ/BK partial reduction (blocks 1024..1151)
__global__ void k_tail(const float* __restrict__ c, const float* __restrict__ dctx,
                       const float* __restrict__ abd_w, const float* __restrict__ abd_b,
                       const float* __restrict__ ctx_w, const float* __restrict__ ctx_b,
                       const float* __restrict__ w1, const float* __restrict__ b1,
                       const float* __restrict__ w_prob, const float* __restrict__ b_prob,
                       float* __restrict__ out) {
    int bn = blockIdx.x;
    int t = threadIdx.x;

    if (bn >= 1024) {
        int rb = bn - 1024;                     // 0..127
#pragma unroll
        for (int it = 0; it < 2; it++) {
            int idx = rb * 256 + it * 128 + t;  // 32768 total
            float sq = 0.f, sk = 0.f;
#pragma unroll
            for (int ks = 0; ks < 32; ks++) {
                sq += g_bqp[ks * (DD * NN) + idx];
                sk += g_bkp[ks * (DD * NN) + idx];
            }
            g_bq[idx] = sq;
            g_bk[idx] = sk;
        }
        return;
    }

    int b = bn >> 6, n = bn & 63;
    __shared__ float s_ct[64], s_cs[64], s_abdj[512], s_d[16];
    __shared__ float red[128], red2[128];
    __shared__ float s_stat[2], s_p[2];

    if (t < QQ) s_d[t] = dctx[bn * QQ + t];
    float v = 0.f;
    if (t < 64) { v = 64.f * c[(size_t)bn * 64 + t]; s_ct[t] = v; }
    __syncthreads();
    if (t < 32) {
        float m = fmaxf(s_ct[t], s_ct[t + 32]);
#pragma unroll
        for (int o = 16; o > 0; o >>= 1) m = fmaxf(m, __shfl_xor_sync(0xffffffffu, m, o));
        if (t == 0) s_stat[0] = m;
    }
    __syncthreads();
    float e = 0.f;
    if (t < 64) e = expf(v - s_stat[0]);
    red[t] = (t < 64) ? e : 0.f;
    __syncthreads();
    if (t < 32) {
        float s = red[t] + red[t + 32];
#pragma unroll
        for (int o = 16; o > 0; o >>= 1) s += __shfl_xor_sync(0xffffffffu, s, o);
        if (t == 0) s_stat[1] = s;
    }
    __syncthreads();
    if (t < 64) {
        float ct = e / s_stat[1];
        s_ct[t] = ct;
        out[OFF_CT + (long long)bn * 64 + t] = ct;
    }
    __syncthreads();

    if (t < 64) {
        float acc = b1[n * 64 + t];
        const float* w1r = w1 + ((size_t)n * 64 + t) * 64;
#pragma unroll 8
        for (int p = 0; p < 64; p++) acc += s_ct[p] * w1r[p];
        float cs = fmaxf(acc, 0.f);
        s_cs[t] = cs;
        out[OFF_CS + (long long)bn * 64 + t] = cs;
    }
    for (int d = t; d < DD; d += 128) {
        float dp = ctx_b[d];
        const float* cw = ctx_w + d * QQ;
#pragma unroll
        for (int q = 0; q < QQ; q++) dp += s_d[q] * cw[q];
        float abn = out[OFF_ABN + (long long)b * DD + d];
        float val = tanhf(abd_w[n * DD + d] * abn * dp + abd_b[n * DD + d]);
        s_abdj[d] = val;
        out[OFF_ABDJ + (long long)bn * DD + d] = val;
    }
    __syncthreads();

    float l0 = 0.f, l1 = 0.f;
    const float* wp0 = w_prob + (size_t)(n * 2 + 0) * 576;
    const float* wp1 = w_prob + (size_t)(n * 2 + 1) * 576;
    for (int k = t; k < 576; k += 128) {
        float cb = (k < 64) ? s_cs[k] : s_abdj[k - 64];
        l0 += cb * wp0[k];
        l1 += cb * wp1[k];
    }
    red[t] = l0; red2[t] = l1;
    __syncthreads();
    for (int s = 64; s > 0; s >>= 1) {
        if (t < s) { red[t] += red[t + s]; red2[t] += red2[t + s]; }
        __syncthreads();
    }
    if (t == 0) {
        float L0 = red[0] + b_prob[n * 2 + 0];
        float L1 = red2[0] + b_prob[n * 2 + 1];
        float m = fmaxf(L0, L1);
        float e0 = expf(L0 - m), e1 = expf(L1 - m);
        float inv = 1.f / (e0 + e1);
        s_p[0] = e0 * inv; s_p[1] = e1 * inv;
        out[OFF_PHAT + (long long)bn * 2 + 0] = s_p[0];
        out[OFF_PHAT + (long long)bn * 2 + 1] = s_p[1];
    }
    __syncthreads();
    if (t < 64) {
        float cs = s_cs[t];
        out[OFF_CDBL + (long long)bn * 64 + t] = tanhf(s_p[0] * cs) + tanhf(s_p[1] * cs);
    }
}

// ---------------------------------------------------------------------------
// K_proj: q_proj/k_proj = s3*(wqd[b] @ c[b]^T) + tb*BQ.  grid=(16,16), block=(16,16)
__global__ void k_proj(const float* __restrict__ c, const float* __restrict__ alpha,
                       float* __restrict__ out) {
    __shared__ float sc[64 * 65];
    __shared__ float swq[32 * 65];
    __shared__ float swk[32 * 65];
    int dt = blockIdx.x, b = blockIdx.y;
    int tx = threadIdx.x, ty = threadIdx.y;
    int tid = ty * 16 + tx;
    float ap = 1.f + alpha[0];
    float s3 = ap * ap * ap;
    float tb = ap * ap + ap + 1.f;

#pragma unroll
    for (int it = 0; it < 4; it++) {
        int idx = tid + 256 * it;
        int r = idx >> 4, cv = idx & 15;
        float4 v = *(const float4*)(c + (size_t)(b * NN + r) * PP + cv * 4);
        sc[r * 65 + cv * 4 + 0] = v.x; sc[r * 65 + cv * 4 + 1] = v.y;
        sc[r * 65 + cv * 4 + 2] = v.z; sc[r * 65 + cv * 4 + 3] = v.w;
    }
#pragma unroll
    for (int it = 0; it < 2; it++) {
        int idx = tid + 256 * it;
        int r = idx >> 4, cv = idx & 15;
        size_t src = (size_t)b * (DD * PP) + (size_t)(dt * 32 + r) * PP + cv * 4;
        float4 q = *(const float4*)(g_wqd + src);
        float4 k = *(const float4*)(g_wkd + src);
        swq[r * 65 + cv * 4 + 0] = q.x; swq[r * 65 + cv * 4 + 1] = q.y;
        swq[r * 65 + cv * 4 + 2] = q.z; swq[r * 65 + cv * 4 + 3] = q.w;
        swk[r * 65 + cv * 4 + 0] = k.x; swk[r * 65 + cv * 4 + 1] = k.y;
        swk[r * 65 + cv * 4 + 2] = k.z; swk[r * 65 + cv * 4 + 3] = k.w;
    }
    __syncthreads();

    float accq[2][4] = {}, acck[2][4] = {};
    for (int p = 0; p < PP; p++) {
        float aq[2], ak[2], bv[4];
#pragma unroll
        for (int i = 0; i < 2; i++) {
            aq[i] = swq[(ty * 2 + i) * 65 + p];
            ak[i] = swk[(ty * 2 + i) * 65 + p];
        }
#pragma unroll
        for (int j = 0; j < 4; j++) bv[j] = sc[(tx * 4 + j) * 65 + p];
#pragma unroll
        for (int i = 0; i < 2; i++)
#pragma unroll
            for (int j = 0; j < 4; j++) {
                accq[i][j] += aq[i] * bv[j];
                acck[i][j] += ak[i] * bv[j];
            }
    }
#pragma unroll
    for (int i = 0; i < 2; i++)
#pragma unroll
        for (int j = 0; j < 4; j++) {
            int d = dt * 32 + ty * 2 + i;
            int n = tx * 4 + j;
            long long o = (long long)b * (DD * NN) + d * NN + n;
            out[OFF_Q + o] = s3 * accq[i][j] + tb * g_bq[d * NN + n];
            out[OFF_K + o] = s3 * acck[i][j] + tb * g_bk[d * NN + n];
        }
}

// ---------------------------------------------------------------------------
// K_big: the HBM-bound kernel — m and m_p (537 MB of stores).
// grid = N*B = 1024 blocks, i-outer so concurrent blocks share bias[i] in L2.
__global__ void k_big(const float* __restrict__ c, const float* __restrict__ dctx,
                      const float* __restrict__ bias, const float* __restrict__ alpha,
                      float* __restrict__ out) {
    int i = blockIdx.x >> 4;     // 0..63
    int b = blockIdx.x & 15;     // 0..15
    int t = threadIdx.x;
    float ap = 1.f + alpha[0];
    float s3 = ap * ap * ap;
    float tb = ap * ap + ap + 1.f;

    __shared__ float4 ds[256];  // d_ctx[b] : 64 rows x 16 floats = 256 float4
    ds[t] = ((const float4*)(dctx + (size_t)b * NN * QQ))[t];

    int p = t >> 2;
    int qv = t & 3;
    float cv = c[((size_t)b * NN + i) * PP + p];
    __syncthreads();

    const float4* bias4 = (const float4*)bias + (size_t)i * (NN * CELL / 4);
    float4* m4 = (float4*)out + ((size_t)b * NN + i) * (NN * CELL / 4);
    float4* mp4 = m4 + (OFF_MP / 4);

#pragma unroll 4
    for (int j = 0; j < NN; j++) {
        float4 d4 = ds[j * 4 + qv];
        float4 mv;
        mv.x = cv * d4.x; mv.y = cv * d4.y; mv.z = cv * d4.z; mv.w = cv * d4.w;
        float4 bv = __ldg(&bias4[j * 256 + t]);
        float4 mp;
        mp.x = s3 * mv.x + tb * bv.x;
        mp.y = s3 * mv.y + tb * bv.y;
        mp.z = s3 * mv.z + tb * bv.z;
        mp.w = s3 * mv.w + tb * bv.w;
        __stcs(&m4[j * 256 + t], mv);
        __stcs(&mp4[j * 256 + t], mp);
    }
}

// ---------------------------------------------------------------------------
extern "C" void kernel_launch(void* const* d_in, const int* in_sizes, int n_in,
                              void* d_out, int out_size) {
    const float* a      = (const float*)d_in[0];
    const float* b      = (const float*)d_in[1];
    const float* c      = (const float*)d_in[2];
    const float* dctx   = (const float*)d_in[3];
    const float* alpha  = (const float*)d_in[4];
    const float* bias   = (const float*)d_in[5];
    const float* wq     = (const float*)d_in[6];
    const float* wk     = (const float*)d_in[7];
    const float* abd_w  = (const float*)d_in[8];
    const float* abd_b  = (const float*)d_in[9];
    const float* ctx_w  = (const float*)d_in[10];
    const float* ctx_b  = (const float*)d_in[11];
    const float* w1     = (const float*)d_in[12];
    const float* b1     = (const float*)d_in[13];
    const float* w_prob = (const float*)d_in[14];
    const float* b_prob = (const float*)d_in[15];
    float* out = (float*)d_out;

    // One-time stream/event creation on the (uncaptured) correctness call.
    static cudaStream_t s2 = []() {
        cudaStream_t s; cudaStreamCreateWithFlags(&s, cudaStreamNonBlocking); return s;
    }();
    static cudaEvent_t evFork = []() {
        cudaEvent_t e; cudaEventCreateWithFlags(&e, cudaEventDisableTiming); return e;
    }();
    static cudaEvent_t evJoin = []() {
        cudaEvent_t e; cudaEventCreateWithFlags(&e, cudaEventDisableTiming); return e;
    }();

    // Fork: small-kernel chain on s2, overlapped with k_big on the main stream.
    cudaEventRecord(evFork, 0);
    cudaStreamWaitEvent(s2, evFork, 0);

    k_pre<<<2320, 256, 0, s2>>>(a, b, dctx, bias, wq, wk, out);
    k_bqpart<<<dim3(16, 32), dim3(16, 8), 0, s2>>>(wq, wk);
    k_tail<<<1152, 128, 0, s2>>>(c, dctx, abd_w, abd_b, ctx_w, ctx_b,
                                 w1, b1, w_prob, b_prob, out);
    k_proj<<<dim3(16, 16), dim3(16, 16), 0, s2>>>(c, alpha, out);
    cudaEventRecord(evJoin, s2);

    // Main stream: the HBM-bound giant.
    k_big<<<NN * BB, 256>>>(c, dctx, bias, alpha, out);

    // Join back into the capture-origin stream.
    cudaStreamWaitEvent(0, evJoin, 0);
}

// round 4
// speedup vs baseline: 1.2350x; 1.0372x over previous
#include <cuda_runtime.h>
#include <cstdint>
#include <math.h>

// Problem dims
#define BB 16
#define NN 64
#define DD 512
#define PP 64
#define QQ 16
#define CELL 1024   // PP*QQ

// Output offsets (flat concat of reference return tuple, fp32)
#define OFF_M     0LL
#define OFF_MP    67108864LL
#define OFF_Q     134217728LL
#define OFF_K     134742016LL
#define OFF_COS   135266304LL
#define OFF_ABN   135266320LL
#define OFF_ABDJ  135274512LL
#define OFF_CT    135798800LL
#define OFF_CS    135864336LL
#define OFF_CDBL  135929872LL
#define OFF_PHAT  135995408LL

// Scratch (__device__ globals: allocation-free)
__device__ float g_bias_bar[NN * CELL];           // mean_j bias_m[i,j,c]
__device__ float g_wqd[BB * DD * PP];             // sum_q dbar*w_q
__device__ float g_wkd[BB * DD * PP];
__device__ float g_bqp[32 * DD * NN];             // K-split partials of bias_bar @ w_q^T
__device__ float g_bkp[32 * DD * NN];
__device__ float g_bq[DD * NN];
__device__ float g_bk[DD * NN];

// ---------------------------------------------------------------------------
// K_pre: fused independent preprocessing. grid = 16 + 256 + 2048, block=256
__global__ void k_pre(const float* __restrict__ a, const float* __restrict__ b_,
                      const float* __restrict__ dctx, const float* __restrict__ bias,
                      const float* __restrict__ wq, const float* __restrict__ wk,
                      float* __restrict__ out) {
    int blk = blockIdx.x;
    int t = threadIdx.x;

    if (blk < 16) {
        int b = blk;
        __shared__ float ra[256], rb[256], rab[256];
        __shared__ float s_cos;
        float sa = 0.f, sb = 0.f, sab = 0.f;
        for (int d = t; d < DD; d += 256) {
            float av = a[b * DD + d], bv = b_[b * DD + d];
            sa += av * av; sb += bv * bv; sab += av * bv;
        }
        ra[t] = sa; rb[t] = sb; rab[t] = sab;
        __syncthreads();
        for (int s = 128; s > 0; s >>= 1) {
            if (t < s) { ra[t] += ra[t + s]; rb[t] += rb[t + s]; rab[t] += rab[t + s]; }
            __syncthreads();
        }
        if (t == 0) {
            float na = fmaxf(sqrtf(ra[0]), 1e-8f);
            float nb = fmaxf(sqrtf(rb[0]), 1e-8f);
            float cosv = rab[0] / (na * nb);
            s_cos = cosv;
            out[OFF_COS + b] = cosv;
        }
        __syncthreads();
        float cosv = s_cos;
        for (int d = t; d < DD; d += 256) {
            out[OFF_ABN + (long long)b * DD + d] =
                tanhf(a[b * DD + d] * (1.f - cosv)) + tanhf(b_[b * DD + d] * cosv);
        }
    } else if (blk < 272) {
        int idx = (blk - 16) * 256 + t;        // 65536 total
        int i = idx >> 10, c = idx & 1023;
        float s = 0.f;
        const float* base = bias + (size_t)i * NN * CELL + c;
#pragma unroll 8
        for (int j = 0; j < NN; j++) s += base[(size_t)j * CELL];
        g_bias_bar[idx] = s * (1.f / NN);
    } else {
        int blk2 = blk - 272;                  // 0..2047
        int gid0 = blk2 * 256;
        int b = gid0 >> 15;                    // constant per block
        __shared__ float s_part[256];
        __shared__ float s_dbar[16];
        {
            int q = t & 15, g = t >> 4;
            const float* dbase = dctx + (size_t)b * NN * QQ;
            float s = 0.f;
#pragma unroll
            for (int jj = 0; jj < 4; jj++) s += dbase[(g * 4 + jj) * QQ + q];
            s_part[t] = s;
            __syncthreads();
            if (t < 16) {
                float acc = 0.f;
#pragma unroll
                for (int gg = 0; gg < 16; gg++) acc += s_part[gg * 16 + t];
                s_dbar[t] = acc * (1.f / NN);
            }
            __syncthreads();
        }
        int gid = gid0 + t;
        int dp = gid & 32767;
        int d = dp >> 6, p = dp & 63;
        const float* wqr = wq + (size_t)d * CELL + p * QQ;
        const float* wkr = wk + (size_t)d * CELL + p * QQ;
        float sq = 0.f, sk = 0.f;
#pragma unroll
        for (int q = 0; q < QQ; q++) {
            float dv = s_dbar[q];
            sq += dv * wqr[q];
            sk += dv * wkr[q];
        }
        g_wqd[gid] = sq;
        g_wkd[gid] = sk;
    }
}

// ---------------------------------------------------------------------------
// K_bq: BQ/BK partials, K-split 32 (K=32 each). grid=(16 dt, 32 ks), block=(16,8)
__global__ void k_bqpart(const float* __restrict__ wq, const float* __restrict__ wk) {
    __shared__ float sb[64 * 33];
    __shared__ float swq[32 * 33];
    __shared__ float swk[32 * 33];
    int dt = blockIdx.x, ks = blockIdx.y;
    int tx = threadIdx.x, ty = threadIdx.y;
    int tid = ty * 16 + tx;          // 0..127
    int k0 = ks * 32;

#pragma unroll
    for (int it = 0; it < 4; it++) {
        int idx = tid + 128 * it;
        int r = idx >> 3, cv = idx & 7;
        float4 v = *(const float4*)(g_bias_bar + r * CELL + k0 + cv * 4);
        sb[r * 33 + cv * 4 + 0] = v.x; sb[r * 33 + cv * 4 + 1] = v.y;
        sb[r * 33 + cv * 4 + 2] = v.z; sb[r * 33 + cv * 4 + 3] = v.w;
    }
#pragma unroll
    for (int it = 0; it < 2; it++) {
        int idx = tid + 128 * it;
        int r = idx >> 3, cv = idx & 7;
        float4 q = *(const float4*)(wq + (size_t)(dt * 32 + r) * CELL + k0 + cv * 4);
        float4 k = *(const float4*)(wk + (size_t)(dt * 32 + r) * CELL + k0 + cv * 4);
        swq[r * 33 + cv * 4 + 0] = q.x; swq[r * 33 + cv * 4 + 1] = q.y;
        swq[r * 33 + cv * 4 + 2] = q.z; swq[r * 33 + cv * 4 + 3] = q.w;
        swk[r * 33 + cv * 4 + 0] = k.x; swk[r * 33 + cv * 4 + 1] = k.y;
        swk[r * 33 + cv * 4 + 2] = k.z; swk[r * 33 + cv * 4 + 3] = k.w;
    }
    __syncthreads();

    float accq[4][4] = {}, acck[4][4] = {};
    for (int kk = 0; kk < 32; kk++) {
        float aq[4], ak[4], bv[4];
#pragma unroll
        for (int i = 0; i < 4; i++) {
            aq[i] = swq[(ty * 4 + i) * 33 + kk];
            ak[i] = swk[(ty * 4 + i) * 33 + kk];
        }
#pragma unroll
        for (int j = 0; j < 4; j++) bv[j] = sb[(tx * 4 + j) * 33 + kk];
#pragma unroll
        for (int i = 0; i < 4; i++)
#pragma unroll
            for (int j = 0; j < 4; j++) {
                accq[i][j] += aq[i] * bv[j];
                acck[i][j] += ak[i] * bv[j];
            }
    }
#pragma unroll
    for (int i = 0; i < 4; i++)
#pragma unroll
        for (int j = 0; j < 4; j++) {
            int d = dt * 32 + ty * 4 + i;
            int n = tx * 4 + j;
            g_bqp[ks * (DD * NN) + d * NN + n] = accq[i][j];
            g_bkp[ks * (DD * NN) + d * NN + n] = acck[i][j];
        }
}

// ---------------------------------------------------------------------------
// K_tail: tail math (blocks <1024) + BQ/BK partial reduction (blocks 1024..1151)
__global__ void k_tail(const float* __restrict__ c, const float* __restrict__ dctx,
                       const float* __restrict__ abd_w, const float* __restrict__ abd_b,
                       const float* __restrict__ ctx_w, const float* __restrict__ ctx_b,
                       const float* __restrict__ w1, const float* __restrict__ b1,
                       const float* __restrict__ w_prob, const float* __restrict__ b_prob,
                       float* __restrict__ out) {
    int bn = blockIdx.x;
    int t = threadIdx.x;

    if (bn >= 1024) {
        int rb = bn - 1024;                     // 0..127
#pragma unroll
        for (int it = 0; it < 2; it++) {
            int idx = rb * 256 + it * 128 + t;  // 32768 total
            float sq = 0.f, sk = 0.f;
#pragma unroll
            for (int ks = 0; ks < 32; ks++) {
                sq += g_bqp[ks * (DD * NN) + idx];
                sk += g_bkp[ks * (DD * NN) + idx];
            }
            g_bq[idx] = sq;
            g_bk[idx] = sk;
        }
        return;
    }

    int b = bn >> 6, n = bn & 63;
    __shared__ float s_ct[64], s_cs[64], s_abdj[512], s_d[16];
    __shared__ float red[128], red2[128];
    __shared__ float s_stat[2], s_p[2];

    if (t < QQ) s_d[t] = dctx[bn * QQ + t];
    float v = 0.f;
    if (t < 64) { v = 64.f * c[(size_t)bn * 64 + t]; s_ct[t] = v; }
    __syncthreads();
    if (t < 32) {
        float m = fmaxf(s_ct[t], s_ct[t + 32]);
#pragma unroll
        for (int o = 16; o > 0; o >>= 1) m = fmaxf(m, __shfl_xor_sync(0xffffffffu, m, o));
        if (t == 0) s_stat[0] = m;
    }
    __syncthreads();
    float e = 0.f;
    if (t < 64) e = expf(v - s_stat[0]);
    red[t] = (t < 64) ? e : 0.f;
    __syncthreads();
    if (t < 32) {
        float s = red[t] + red[t + 32];
#pragma unroll
        for (int o = 16; o > 0; o >>= 1) s += __shfl_xor_sync(0xffffffffu, s, o);
        if (t == 0) s_stat[1] = s;
    }
    __syncthreads();
    if (t < 64) {
        float ct = e / s_stat[1];
        s_ct[t] = ct;
        out[OFF_CT + (long long)bn * 64 + t] = ct;
    }
    __syncthreads();

    if (t < 64) {
        float acc = b1[n * 64 + t];
        const float* w1r = w1 + ((size_t)n * 64 + t) * 64;
#pragma unroll 8
        for (int p = 0; p < 64; p++) acc += s_ct[p] * w1r[p];
        float cs = fmaxf(acc, 0.f);
        s_cs[t] = cs;
        out[OFF_CS + (long long)bn * 64 + t] = cs;
    }
    for (int d = t; d < DD; d += 128) {
        float dp = ctx_b[d];
        const float* cw = ctx_w + d * QQ;
#pragma unroll
        for (int q = 0; q < QQ; q++) dp += s_d[q] * cw[q];
        float abn = out[OFF_ABN + (long long)b * DD + d];
        float val = tanhf(abd_w[n * DD + d] * abn * dp + abd_b[n * DD + d]);
        s_abdj[d] = val;
        out[OFF_ABDJ + (long long)bn * DD + d] = val;
    }
    __syncthreads();

    float l0 = 0.f, l1 = 0.f;
    const float* wp0 = w_prob + (size_t)(n * 2 + 0) * 576;
    const float* wp1 = w_prob + (size_t)(n * 2 + 1) * 576;
    for (int k = t; k < 576; k += 128) {
        float cb = (k < 64) ? s_cs[k] : s_abdj[k - 64];
        l0 += cb * wp0[k];
        l1 += cb * wp1[k];
    }
    red[t] = l0; red2[t] = l1;
    __syncthreads();
    for (int s = 64; s > 0; s >>= 1) {
        if (t < s) { red[t] += red[t + s]; red2[t] += red2[t + s]; }
        __syncthreads();
    }
    if (t == 0) {
        float L0 = red[0] + b_prob[n * 2 + 0];
        float L1 = red2[0] + b_prob[n * 2 + 1];
        float m = fmaxf(L0, L1);
        float e0 = expf(L0 - m), e1 = expf(L1 - m);
        float inv = 1.f / (e0 + e1);
        s_p[0] = e0 * inv; s_p[1] = e1 * inv;
        out[OFF_PHAT + (long long)bn * 2 + 0] = s_p[0];
        out[OFF_PHAT + (long long)bn * 2 + 1] = s_p[1];
    }
    __syncthreads();
    if (t < 64) {
        float cs = s_cs[t];
        out[OFF_CDBL + (long long)bn * 64 + t] = tanhf(s_p[0] * cs) + tanhf(s_p[1] * cs);
    }
}

// ---------------------------------------------------------------------------
// K_proj: q_proj/k_proj = s3*(wqd[b] @ c[b]^T) + tb*BQ.  grid=(16,16), block=(16,16)
__global__ void k_proj(const float* __restrict__ c, const float* __restrict__ alpha,
                       float* __restrict__ out) {
    __shared__ float sc[64 * 65];
    __shared__ float swq[32 * 65];
    __shared__ float swk[32 * 65];
    int dt = blockIdx.x, b = blockIdx.y;
    int tx = threadIdx.x, ty = threadIdx.y;
    int tid = ty * 16 + tx;
    float ap = 1.f + alpha[0];
    float s3 = ap * ap * ap;
    float tb = ap * ap + ap + 1.f;

#pragma unroll
    for (int it = 0; it < 4; it++) {
        int idx = tid + 256 * it;
        int r = idx >> 4, cv = idx & 15;
        float4 v = *(const float4*)(c + (size_t)(b * NN + r) * PP + cv * 4);
        sc[r * 65 + cv * 4 + 0] = v.x; sc[r * 65 + cv * 4 + 1] = v.y;
        sc[r * 65 + cv * 4 + 2] = v.z; sc[r * 65 + cv * 4 + 3] = v.w;
    }
#pragma unroll
    for (int it = 0; it < 2; it++) {
        int idx = tid + 256 * it;
        int r = idx >> 4, cv = idx & 15;
        size_t src = (size_t)b * (DD * PP) + (size_t)(dt * 32 + r) * PP + cv * 4;
        float4 q = *(const float4*)(g_wqd + src);
        float4 k = *(const float4*)(g_wkd + src);
        swq[r * 65 + cv * 4 + 0] = q.x; swq[r * 65 + cv * 4 + 1] = q.y;
        swq[r * 65 + cv * 4 + 2] = q.z; swq[r * 65 + cv * 4 + 3] = q.w;
        swk[r * 65 + cv * 4 + 0] = k.x; swk[r * 65 + cv * 4 + 1] = k.y;
        swk[r * 65 + cv * 4 + 2] = k.z; swk[r * 65 + cv * 4 + 3] = k.w;
    }
    __syncthreads();

    float accq[2][4] = {}, acck[2][4] = {};
    for (int p = 0; p < PP; p++) {
        float aq[2], ak[2], bv[4];
#pragma unroll
        for (int i = 0; i < 2; i++) {
            aq[i] = swq[(ty * 2 + i) * 65 + p];
            ak[i] = swk[(ty * 2 + i) * 65 + p];
        }
#pragma unroll
        for (int j = 0; j < 4; j++) bv[j] = sc[(tx * 4 + j) * 65 + p];
#pragma unroll
        for (int i = 0; i < 2; i++)
#pragma unroll
            for (int j = 0; j < 4; j++) {
                accq[i][j] += aq[i] * bv[j];
                acck[i][j] += ak[i] * bv[j];
            }
    }
#pragma unroll
    for (int i = 0; i < 2; i++)
#pragma unroll
        for (int j = 0; j < 4; j++) {
            int d = dt * 32 + ty * 2 + i;
            int n = tx * 4 + j;
            long long o = (long long)b * (DD * NN) + d * NN + n;
            out[OFF_Q + o] = s3 * accq[i][j] + tb * g_bq[d * NN + n];
            out[OFF_K + o] = s3 * acck[i][j] + tb * g_bk[d * NN + n];
        }
}

// ---------------------------------------------------------------------------
// K_big v2: one block per (i, j-chunk of 4). Bias slice staged in smem ONCE,
// then all 16 b values processed from smem. Global bias reads: 16.8 MB total.
// grid = 64*16 = 1024 blocks, block = 256, smem = 24 KB.
__global__ void __launch_bounds__(256) k_big(
        const float* __restrict__ c, const float* __restrict__ dctx,
        const float* __restrict__ bias, const float* __restrict__ alpha,
        float* __restrict__ out) {
    int i  = blockIdx.x >> 4;    // 0..63
    int jc = blockIdx.x & 15;    // 0..15
    int j0 = jc * 4;
    int t = threadIdx.x;

    __shared__ float s_bias[4 * 1024];   // bias[i, j0..j0+3, :]
    __shared__ float s_d[16 * 4 * 16];   // d_ctx[b, j0..j0+3, :]
    __shared__ float s_c[16 * 64];       // c[b, i, :]

    float ap = 1.f + alpha[0];
    float s3 = ap * ap * ap;
    float tb = ap * ap + ap + 1.f;

    // bias slice: 4096 floats = 1024 float4
    {
        const float4* src = (const float4*)(bias + ((size_t)i * NN + j0) * CELL);
        float4* dst = (float4*)s_bias;
#pragma unroll
        for (int it = 0; it < 4; it++) dst[t + 256 * it] = src[t + 256 * it];
    }
    // d_ctx slice: 16b x 4j x 16q = 1024 floats = 256 float4
    {
        int b = t >> 4, j = (t >> 2) & 3, qv = t & 3;
        ((float4*)s_d)[t] = *(const float4*)(dctx + ((size_t)b * NN + j0 + j) * QQ + qv * 4);
    }
    // c slice: 16b x 64p = 1024 floats = 256 float4
    {
        int b = t >> 4, pv = t & 15;
        ((float4*)s_c)[t] = *(const float4*)(c + ((size_t)b * NN + i) * PP + pv * 4);
    }
    __syncthreads();

    int p = t >> 2;
    int qv = t & 3;
    float4* outbase = (float4*)out;
    const float4* sd4 = (const float4*)s_d;
    const float4* sb4 = (const float4*)s_bias;

    for (int b = 0; b < BB; b++) {
        float cv = s_c[b * 64 + p];
        size_t row = ((size_t)(b * NN + i) * NN + j0) * 256;   // float4 units
#pragma unroll
        for (int j = 0; j < 4; j++) {
            float4 d4 = sd4[(b * 4 + j) * 4 + qv];
            float4 bv = sb4[j * 256 + t];
            float4 mv;
            mv.x = cv * d4.x; mv.y = cv * d4.y; mv.z = cv * d4.z; mv.w = cv * d4.w;
            float4 mp;
            mp.x = s3 * mv.x + tb * bv.x;
            mp.y = s3 * mv.y + tb * bv.y;
            mp.z = s3 * mv.z + tb * bv.z;
            mp.w = s3 * mv.w + tb * bv.w;
            __stcs(&outbase[row + j * 256 + t], mv);
            __stcs(&outbase[(OFF_MP / 4) + row + j * 256 + t], mp);
        }
    }
}

// ---------------------------------------------------------------------------
extern "C" void kernel_launch(void* const* d_in, const int* in_sizes, int n_in,
                              void* d_out, int out_size) {
    const float* a      = (const float*)d_in[0];
    const float* b      = (const float*)d_in[1];
    const float* c      = (const float*)d_in[2];
    const float* dctx   = (const float*)d_in[3];
    const float* alpha  = (const float*)d_in[4];
    const float* bias   = (const float*)d_in[5];
    const float* wq     = (const float*)d_in[6];
    const float* wk     = (const float*)d_in[7];
    const float* abd_w  = (const float*)d_in[8];
    const float* abd_b  = (const float*)d_in[9];
    const float* ctx_w  = (const float*)d_in[10];
    const float* ctx_b  = (const float*)d_in[11];
    const float* w1     = (const float*)d_in[12];
    const float* b1     = (const float*)d_in[13];
    const float* w_prob = (const float*)d_in[14];
    const float* b_prob = (const float*)d_in[15];
    float* out = (float*)d_out;

    // One-time stream/event creation on the (uncaptured) correctness call.
    // Chain stream gets highest priority so its latency-bound blocks are
    // scheduled promptly underneath k_big.
    static cudaStream_t s2 = []() {
        int lo, hi;
        cudaDeviceGetStreamPriorityRange(&lo, &hi);   // hi = most urgent (lowest num)
        cudaStream_t s;
        cudaStreamCreateWithPriority(&s, cudaStreamNonBlocking, hi);
        return s;
    }();
    static cudaEvent_t evFork = []() {
        cudaEvent_t e; cudaEventCreateWithFlags(&e, cudaEventDisableTiming); return e;
    }();
    static cudaEvent_t evJoin = []() {
        cudaEvent_t e; cudaEventCreateWithFlags(&e, cudaEventDisableTiming); return e;
    }();

    // Fork: small-kernel chain on s2 (high prio), overlapped with k_big.
    cudaEventRecord(evFork, 0);
    cudaStreamWaitEvent(s2, evFork, 0);

    k_pre<<<2320, 256, 0, s2>>>(a, b, dctx, bias, wq, wk, out);
    k_bqpart<<<dim3(16, 32), dim3(16, 8), 0, s2>>>(wq, wk);
    k_tail<<<1152, 128, 0, s2>>>(c, dctx, abd_w, abd_b, ctx_w, ctx_b,
                                 w1, b1, w_prob, b_prob, out);
    k_proj<<<dim3(16, 16), dim3(16, 16), 0, s2>>>(c, alpha, out);
    cudaEventRecord(evJoin, s2);

    // Main stream: the HBM-bound giant.
    k_big<<<1024, 256>>>(c, dctx, bias, alpha, out);

    // Join back into the capture-origin stream.
    cudaStreamWaitEvent(0, evJoin, 0);
}